// round 15
// baseline (speedup 1.0000x reference)
#include <cuda_runtime.h>
#include <math.h>

#define D_FEAT 8192
#define T_RES  2048
#define ORDER  16
#define DTAU   0.08
#define REG    0.0001f
#define EPS_C  1e-15f

#define ROW_BLOCKS 512   // k_A: 4 rows/block, 2 warps per row
#define NW  256
#define NWC 512
#define RI_STRIDE4 (D_FEAT / 8)   // int4 per row of the int16 matrix (1024)

// ---------------- device scratch (no allocations allowed) ----------------
__device__ short g_Ri[T_RES * D_FEAT];        // int16 row-scaled R (32 MB)
__device__ float g_rs[T_RES];                 // dequant scale  = rowmax/32767
__device__ float g_rsq[T_RES];                // quant scale    = 32767/rowmax
__device__ float g_s[ORDER * T_RES];          // s_j = R~ q_j
__device__ float g_sf[T_RES];                 // R~ f
__device__ float g_Q[ORDER * D_FEAT];         // Lanczos basis
__device__ float g_wf[D_FEAT];                // current unnormalized basis vector
__device__ float g_upart[4 * D_FEAT];         // t-quarter partials of u = R~^T s_j
__device__ float g_nrm2_part[128];            // ||wf||^2 partials
__device__ float g_cpart[ROW_BLOCKS * ORDER]; // per-row-block partials of c_k
__device__ float g_b[ORDER + 1];              // g_b[0]=||F||, g_b[j]=beta[j-1]
__device__ float g_alpha[ORDER];

// int16-R loads: non-coherent + L2 evict_last policy. 32 MB << 126 MB L2, so
// R~ stays fully L2-resident across all sweeps.
__device__ __forceinline__ unsigned long long mk_pol() {
    unsigned long long p;
    asm("createpolicy.fractional.L2::evict_last.b64 %0, 1.0;" : "=l"(p));
    return p;
}
__device__ __forceinline__ int4 ldRi(const int4* p, unsigned long long pol) {
    int4 v;
    asm volatile("ld.global.nc.L2::cache_hint.v4.b32 {%0,%1,%2,%3}, [%4], %5;"
                 : "=r"(v.x), "=r"(v.y), "=r"(v.z), "=r"(v.w)
                 : "l"(p), "l"(pol));
    return v;
}
// unpack one 32-bit word (2 shorts) and fma with 2 fp32 weights
__device__ __forceinline__ void dq2(float& acc, int w, float q0, float q1) {
    short lo = (short)(w & 0xffff), hi = (short)(w >> 16);
    acc = fmaf((float)lo, q0, acc);
    acc = fmaf((float)hi, q1, acc);
}

// ================= quantization prologue =================
__global__ void k_rowmax(const float* __restrict__ R) {
    int tx = threadIdx.x, lane = tx & 31, w = tx >> 5;
    int r = blockIdx.x * 8 + w;
    const float4* R4 = (const float4*)(R + (size_t)r * D_FEAT);
    float m = 0.f;
    #pragma unroll 8
    for (int it = 0; it < 64; it++) {
        float4 v = R4[it * 32 + lane];
        m = fmaxf(m, fmaxf(fmaxf(fabsf(v.x), fabsf(v.y)), fmaxf(fabsf(v.z), fabsf(v.w))));
    }
    #pragma unroll
    for (int o = 16; o; o >>= 1) m = fmaxf(m, __shfl_xor_sync(0xffffffffu, m, o));
    if (lane == 0) {
        m = fmaxf(m, 1e-30f);
        g_rs[r]  = m / 32767.0f;
        g_rsq[r] = 32767.0f / m;
    }
}

__global__ void k_quant(const float* __restrict__ R) {
    const float4* R4 = (const float4*)R;
    short4* O4 = (short4*)g_Ri;
    int n4 = T_RES * D_FEAT / 4;
    for (int i = blockIdx.x * blockDim.x + threadIdx.x; i < n4; i += gridDim.x * blockDim.x) {
        int row = i >> 11;            // 2048 float4 per row
        float q = g_rsq[row];
        float4 v = R4[i];
        short4 o;
        o.x = (short)__float2int_rn(v.x * q);
        o.y = (short)__float2int_rn(v.y * q);
        o.z = (short)__float2int_rn(v.z * q);
        o.w = (short)__float2int_rn(v.w * q);
        O4[i] = o;
    }
}

// ================= prologue row: sf = R~ f (warp per row) =================
__global__ void k_row_f(const float* __restrict__ f) {
    int tx = threadIdx.x, lane = tx & 31, w = tx >> 5;
    unsigned long long pol = mk_pol();
    int r = blockIdx.x * 8 + w;
    const int4* Ri4 = (const int4*)(g_Ri + (size_t)r * D_FEAT);
    const float4* f4 = (const float4*)f;
    float a0 = 0.f, a1 = 0.f;
    #pragma unroll 8
    for (int it = 0; it < 32; it++) {
        int i = it * 32 + lane;
        int4 rv = ldRi(Ri4 + i, pol);
        float4 qa = f4[2 * i], qb = f4[2 * i + 1];
        dq2(a0, rv.x, qa.x, qa.y);
        dq2(a1, rv.y, qa.z, qa.w);
        dq2(a0, rv.z, qb.x, qb.y);
        dq2(a1, rv.w, qb.z, qb.w);
    }
    float acc = a0 + a1;
    #pragma unroll
    for (int o = 16; o; o >>= 1) acc += __shfl_xor_sync(0xffffffffu, acc, o);
    if (lane == 0) g_sf[r] = acc * g_rs[r];
}

// ====== prologue col: F = R~^T sf + E f ; wf = F ; ||F||^2 partials ======
// 128 blocks x 512 thr, 64 cols/block, full t range.
__global__ void k_prologue_col(const float* __restrict__ f) {
    __shared__ float s_sm[T_RES];
    __shared__ float4 shA[NWC], shB[NWC];
    __shared__ float sh_r1[16], sh_r2[16];
    __shared__ float shE;
    int tx = threadIdx.x, lane = tx & 31, w = tx >> 5;
    unsigned long long pol = mk_pol();
    const float4* f4 = (const float4*)f;

    // stage scaled sf; per-block redundant ||sf||^2 and ||f||^2
    float ssf = 0.f;
    for (int i = tx; i < T_RES; i += NWC) {
        float v = g_sf[i];
        s_sm[i] = v * g_rs[i];
        ssf = fmaf(v, v, ssf);
    }
    float ff = 0.f;
    for (int i = tx; i < D_FEAT / 4; i += NWC) {
        float4 v = f4[i];
        ff = fmaf(v.x, v.x, fmaf(v.y, v.y, fmaf(v.z, v.z, fmaf(v.w, v.w, ff))));
    }
    #pragma unroll
    for (int o = 16; o; o >>= 1) {
        ssf += __shfl_xor_sync(0xffffffffu, ssf, o);
        ff  += __shfl_xor_sync(0xffffffffu, ff, o);
    }
    if (lane == 0) { sh_r1[w] = ssf; sh_r2[w] = ff; }
    __syncthreads();
    if (tx == 0) {
        float a = 0.f, b = 0.f;
        #pragma unroll
        for (int i = 0; i < 16; i++) { a += sh_r1[i]; b += sh_r2[i]; }
        shE = -a / (b + EPS_C);
    }
    __syncthreads();

    // u[col] = sum_t R~[t][col] * sf'[t]  (64 cols per block)
    int g = tx & 7, s = tx >> 3;          // g: 8 int4 cols, s in [0,64)
    const int4* Ri4 = (const int4*)g_Ri;
    size_t cbase = (size_t)blockIdx.x * 8 + g;
    float a[8];
    #pragma unroll
    for (int k = 0; k < 8; k++) a[k] = 0.f;
    #pragma unroll 4
    for (int it = 0; it < 32; it++) {
        int t = it * 64 + s;
        float sv = s_sm[t];
        int4 rv = ldRi(Ri4 + (size_t)t * RI_STRIDE4 + cbase, pol);
        dq2(a[0], rv.x, sv, 0.f); dq2(a[1], rv.x, 0.f, sv);
        dq2(a[2], rv.y, sv, 0.f); dq2(a[3], rv.y, 0.f, sv);
        dq2(a[4], rv.z, sv, 0.f); dq2(a[5], rv.z, 0.f, sv);
        dq2(a[6], rv.w, sv, 0.f); dq2(a[7], rv.w, 0.f, sv);
    }
    shA[tx] = make_float4(a[0], a[1], a[2], a[3]);
    shB[tx] = make_float4(a[4], a[5], a[6], a[7]);
    #pragma unroll
    for (int off = 256; off >= 8; off >>= 1) {
        __syncthreads();
        if (tx < off) {
            float4 x = shA[tx], y = shA[tx + off];
            x.x += y.x; x.y += y.y; x.z += y.z; x.w += y.w; shA[tx] = x;
            x = shB[tx]; y = shB[tx + off];
            x.x += y.x; x.y += y.y; x.z += y.z; x.w += y.w; shB[tx] = x;
        }
    }
    __syncthreads();

    float nrm = 0.f;
    if (tx < 8) {
        float4 ua = shA[tx], ub = shB[tx];
        int c0 = blockIdx.x * 64 + tx * 8;
        float uv[8] = {ua.x, ua.y, ua.z, ua.w, ub.x, ub.y, ub.z, ub.w};
        #pragma unroll
        for (int k = 0; k < 8; k++) {
            float F = fmaf(shE, f[c0 + k], uv[k]);
            g_wf[c0 + k] = F;
            nrm = fmaf(F, F, nrm);
        }
    }
    if (tx < 32) {
        #pragma unroll
        for (int o = 4; o; o >>= 1) nrm += __shfl_xor_sync(0xffu, nrm, o);
        if (tx == 0) g_nrm2_part[blockIdx.x] = nrm;
    }
}

// == k_A: b=||wf||; s_j = R~*(wf/b); c-partials (4 rows/block, 2 warps/row) ==
__global__ void k_A(int j, int npart) {
    __shared__ float sh_r[8];
    __shared__ float sh_invb;
    __shared__ float shp[8];
    int tx = threadIdx.x, lane = tx & 31, w = tx >> 5;
    unsigned long long pol = mk_pol();

    float p = (tx < npart) ? g_nrm2_part[tx] : 0.f;
    #pragma unroll
    for (int o = 16; o; o >>= 1) p += __shfl_xor_sync(0xffffffffu, p, o);
    if (lane == 0) sh_r[w] = p;
    __syncthreads();
    if (tx == 0) {
        float n = 0.f;
        #pragma unroll
        for (int i = 0; i < 8; i++) n += sh_r[i];
        float b = sqrtf(n);
        if (blockIdx.x == 0) g_b[j] = b;
        sh_invb = 1.0f / fmaxf(b, 1e-30f);
    }
    __syncthreads();

    int r0 = blockIdx.x * 4;
    int row = r0 + (w >> 1), half = w & 1;
    const int4* Ri4 = (const int4*)(g_Ri + (size_t)row * D_FEAT) + half * 512;
    const float4* w4 = (const float4*)g_wf + half * 1024;
    float a0 = 0.f, a1 = 0.f;
    #pragma unroll 8
    for (int it = 0; it < 16; it++) {
        int i = it * 32 + lane;
        int4 rv = ldRi(Ri4 + i, pol);
        float4 qa = w4[2 * i], qb = w4[2 * i + 1];
        dq2(a0, rv.x, qa.x, qa.y);
        dq2(a1, rv.y, qa.z, qa.w);
        dq2(a0, rv.z, qb.x, qb.y);
        dq2(a1, rv.w, qb.z, qb.w);
    }
    float acc = a0 + a1;
    #pragma unroll
    for (int o = 16; o; o >>= 1) acc += __shfl_xor_sync(0xffffffffu, acc, o);
    if (lane == 0) shp[w] = acc;
    __syncthreads();

    if (w == 0) {
        float d = (lane < 8) ? shp[lane] : 0.f;
        d += __shfl_xor_sync(0xffffffffu, d, 1);   // lanes 0,2,4,6: row dots
        float invb = sh_invb;
        float s0 = __shfl_sync(0xffffffffu, d, 0) * g_rs[r0]     * invb;
        float s1 = __shfl_sync(0xffffffffu, d, 2) * g_rs[r0 + 1] * invb;
        float s2 = __shfl_sync(0xffffffffu, d, 4) * g_rs[r0 + 2] * invb;
        float s3 = __shfl_sync(0xffffffffu, d, 6) * g_rs[r0 + 3] * invb;
        if (lane < 4) {
            float sv = (lane == 0) ? s0 : (lane == 1) ? s1 : (lane == 2) ? s2 : s3;
            g_s[j * T_RES + r0 + lane] = sv;
        }
        if (lane < 16) {
            float cp = 0.f;
            if (lane <= j) {
                if (lane == j) {
                    cp = s0 * s0 + s1 * s1 + s2 * s2 + s3 * s3;
                } else {
                    const float* sk = g_s + (size_t)lane * T_RES + r0;
                    cp = sk[0] * s0 + sk[1] * s1 + sk[2] * s2 + sk[3] * s3;
                }
            }
            g_cpart[blockIdx.x * 16 + lane] = cp;
        }
    }
}

// ===== k_B1: u-quarter partials (4 t-quarters x 128 col-blocks, 64 cols) =====
__global__ void k_B1(int j) {
    __shared__ float s_sm[512];
    __shared__ float4 shA[NWC], shB[NWC];
    int tx = threadIdx.x;
    unsigned long long pol = mk_pol();
    int tq = blockIdx.x >> 7;       // t-quarter
    int cb = blockIdx.x & 127;      // column block

    int tbase = tq * 512;
    if (tx < 512) s_sm[tx] = g_s[j * T_RES + tbase + tx] * g_rs[tbase + tx];
    __syncthreads();

    int g = tx & 7, s = tx >> 3;    // s in [0,64)
    const int4* Ri4 = (const int4*)g_Ri + (size_t)tbase * RI_STRIDE4;
    size_t cbase = (size_t)cb * 8 + g;
    float a[8];
    #pragma unroll
    for (int k = 0; k < 8; k++) a[k] = 0.f;
    #pragma unroll
    for (int it = 0; it < 8; it++) {
        int t = it * 64 + s;
        float sv = s_sm[t];
        int4 rv = ldRi(Ri4 + (size_t)t * RI_STRIDE4 + cbase, pol);
        dq2(a[0], rv.x, sv, 0.f); dq2(a[1], rv.x, 0.f, sv);
        dq2(a[2], rv.y, sv, 0.f); dq2(a[3], rv.y, 0.f, sv);
        dq2(a[4], rv.z, sv, 0.f); dq2(a[5], rv.z, 0.f, sv);
        dq2(a[6], rv.w, sv, 0.f); dq2(a[7], rv.w, 0.f, sv);
    }
    shA[tx] = make_float4(a[0], a[1], a[2], a[3]);
    shB[tx] = make_float4(a[4], a[5], a[6], a[7]);
    #pragma unroll
    for (int off = 256; off >= 8; off >>= 1) {
        __syncthreads();
        if (tx < off) {
            float4 x = shA[tx], y = shA[tx + off];
            x.x += y.x; x.y += y.y; x.z += y.z; x.w += y.w; shA[tx] = x;
            x = shB[tx]; y = shB[tx + off];
            x.x += y.x; x.y += y.y; x.z += y.z; x.w += y.w; shB[tx] = x;
        }
    }
    __syncthreads();
    if (tx < 8) {
        float4 ua = shA[tx], ub = shB[tx];
        int c0 = cb * 64 + tx * 8;
        float* up = g_upart + tq * D_FEAT + c0;
        up[0] = ua.x; up[1] = ua.y; up[2] = ua.z; up[3] = ua.w;
        up[4] = ub.x; up[5] = ub.y; up[6] = ub.z; up[7] = ub.w;
    }
}

// ===== k_B2: combine quarters; reorth; Q[j]; new wf; nrm partials; alpha =====
__global__ void k_B2(int j, int last) {
    __shared__ float sh_c[ORDER];
    __shared__ float shn[4];
    int tx = threadIdx.x, lane = tx & 31, w = tx >> 5;

    {   // reduce c-partials (512 row-blocks x 16)
        int k = tx >> 4, i = tx & 15;
        float c = 0.f;
        #pragma unroll 8
        for (int m = 0; m < ROW_BLOCKS / 16; m++)
            c += g_cpart[(m * 16 + i) * 16 + k];
        #pragma unroll
        for (int o = 8; o; o >>= 1) c += __shfl_xor_sync(0xffffffffu, c, o);
        if (i == 0) sh_c[k] = c;
    }
    __syncthreads();

    if (blockIdx.x == 0 && tx == 0) g_alpha[j] = -sh_c[j];
    float invb = 1.0f / fmaxf(g_b[j], 1e-30f);
    int col = blockIdx.x * 128 + tx;

    if (last) {
        if (tx < 128) g_Q[(size_t)j * D_FEAT + col] = g_wf[col] * invb;
        return;
    }

    float nrm = 0.f;
    if (tx < 128) {
        float u = g_upart[col] + g_upart[D_FEAT + col]
                + g_upart[2 * D_FEAT + col] + g_upart[3 * D_FEAT + col];
        float qv = g_wf[col] * invb;
        g_Q[(size_t)j * D_FEAT + col] = qv;
        float wv = -u;
        for (int k = 0; k < j; k++)
            wv = fmaf(sh_c[k], g_Q[(size_t)k * D_FEAT + col], wv);
        wv = fmaf(sh_c[j], qv, wv);
        g_wf[col] = wv;
        nrm = wv * wv;
    }
    #pragma unroll
    for (int o = 16; o; o >>= 1) nrm += __shfl_xor_sync(0xffffffffu, nrm, o);
    if (lane == 0 && w < 4) shn[w] = nrm;
    __syncthreads();
    if (tx == 0) g_nrm2_part[blockIdx.x] = shn[0] + shn[1] + shn[2] + shn[3];
}

// == k_final: expm (inlined, warp0) + dtheta[p] = D[p].dir / (||D[p]||^2+REG) ==
__global__ void k_final(const float* __restrict__ Dm, float* __restrict__ out) {
    __shared__ float sh_a[8], sh_d[8];
    __shared__ float coeffs[ORDER];
    int p = blockIdx.x;
    int tx = threadIdx.x, lane = tx & 31, w = tx >> 5;

    if (w == 0) {  // exp(-T*DTAU) e0 via lane-parallel double Taylor
        double a = 0.0, bl = 0.0, bu = 0.0;
        if (lane < ORDER) a = (double)g_alpha[lane];
        if (lane >= 1 && lane < ORDER) bl = (double)g_b[lane];
        if (lane < ORDER - 1) bu = (double)g_b[lane + 1];
        double v = (lane == 0) ? 1.0 : 0.0, y = v;
        for (int k = 1; k <= 40; k++) {
            double vp = __shfl_up_sync(0xffffffffu, v, 1);
            double vn = __shfl_down_sync(0xffffffffu, v, 1);
            double t = a * v + bl * vp + bu * vn;
            v = t * (-DTAU / (double)k);
            y += v;
        }
        if (lane < ORDER) coeffs[lane] = (float)((double)g_b[0] * y);
    }
    __syncthreads();

    float cf[ORDER];
    #pragma unroll
    for (int l = 0; l < ORDER; l++) cf[l] = coeffs[l];
    const float* Dp = Dm + (size_t)p * D_FEAT;
    float acc = 0.f, den = 0.f;
    for (int d = tx; d < D_FEAT; d += NW) {
        float dir = 0.f;
        #pragma unroll
        for (int l = 0; l < ORDER; l++) dir = fmaf(cf[l], g_Q[(size_t)l * D_FEAT + d], dir);
        float dv = Dp[d];
        acc = fmaf(dv, dir, acc);
        den = fmaf(dv, dv, den);
    }
    #pragma unroll
    for (int o = 16; o; o >>= 1) {
        acc += __shfl_xor_sync(0xffffffffu, acc, o);
        den += __shfl_xor_sync(0xffffffffu, den, o);
    }
    if (lane == 0) { sh_a[w] = acc; sh_d[w] = den; }
    __syncthreads();
    if (tx == 0) {
        float A = 0.f, Dd = 0.f;
        #pragma unroll
        for (int i = 0; i < 8; i++) { A += sh_a[i]; Dd += sh_d[i]; }
        out[p] = A / (Dd + REG);
    }
}

// --------------------------------- launcher ----------------------------------
extern "C" void kernel_launch(void* const* d_in, const int* in_sizes, int n_in,
                              void* d_out, int out_size) {
    (void)out_size;
    const float* f = nullptr;
    const float* R = nullptr;
    const float* Dm = nullptr;
    for (int i = 0; i < n_in; i++) {
        if (in_sizes[i] == D_FEAT)               f  = (const float*)d_in[i];
        else if (in_sizes[i] == T_RES * D_FEAT)  R  = (const float*)d_in[i];
        else if (in_sizes[i] == ORDER * D_FEAT)  Dm = (const float*)d_in[i];
    }

    k_rowmax<<<256, NW>>>(R);
    k_quant<<<512, NW>>>(R);
    k_row_f<<<256, NW>>>(f);
    k_prologue_col<<<128, NWC>>>(f);
    for (int j = 0; j < ORDER; j++) {
        k_A<<<ROW_BLOCKS, NW>>>(j, (j == 0) ? 128 : 64);
        if (j < ORDER - 1) k_B1<<<512, NWC>>>(j);
        k_B2<<<64, NW>>>(j, (j == ORDER - 1) ? 1 : 0);
    }
    k_final<<<ORDER, NW>>>(Dm, (float*)d_out);
}